// round 2
// baseline (speedup 1.0000x reference)
#include <cuda_runtime.h>
#include <math.h>

#define BB 8
#define NN 2000
#define CC 81
#define NPAD 2048
#define METAS 93
#define MAXI 100
#define NTHREADS 1024
#define MAXV_SMEM 1024
#define WMAX 32

typedef unsigned long long u64;

// -------- dynamic smem layout (bytes) --------
#define OFF_KEYS    0        // u64[2048]      16384
#define OFF_OBOX    16384    // float4[2048]   32768 -> 49152
#define OFF_SBOX    49152    // float4[2048]   32768 -> 81920
#define OFF_SIDX    81920    // ushort[2048]    4096 -> 86016
#define OFF_CLS     86016    // uchar[2048]     2048 -> 88064
#define OFF_COMPACT 88064    // ushort[2048]    4096 -> 92160
#define OFF_CCLS    92160    // uchar[2048]     2048 -> 94208
#define OFF_ELIG    94208    // uchar[2048]     2048 -> 96256
#define OFF_OUT     96256    // ushort[128]      256 -> 96512
#define OFF_WARP    96512    // int[32]          128 -> 96640
#define OFF_STATS   96640    // int[8]            32 -> 96672
#define OFF_REMV    96672    // u64[32]          256 -> 96928
#define OFF_MASK    96928    // u64[1024*16]  131072 -> 228000
#define SMEM_BYTES  228000

// fallback mask scratch for V > 1024 (rarely taken)
__device__ u64 g_mask[(size_t)BB * NPAD * WMAX];

// Exact replication of the reference's box refine + clip (fp32, no FMA contraction).
__device__ __forceinline__ float4 refine_box(const float* __restrict__ rois,
                                             const float* __restrict__ bbox,
                                             int base, int cls,
                                             float wy1, float wx1, float wy2, float wx2) {
    float4 rv = ((const float4*)rois)[base];
    float4 dv = ((const float4*)bbox)[(size_t)base * CC + cls];
    float y1 = rv.x, x1 = rv.y, y2 = rv.z, x2 = rv.w;
    float dy = __fmul_rn(dv.x, 0.1f);
    float dx = __fmul_rn(dv.y, 0.1f);
    float dh = __fmul_rn(dv.z, 0.2f);
    float dw = __fmul_rn(dv.w, 0.2f);
    float h = __fsub_rn(y2, y1);
    float w = __fsub_rn(x2, x1);
    float cy = __fadd_rn(__fadd_rn(y1, __fmul_rn(0.5f, h)), __fmul_rn(dy, h));
    float cx = __fadd_rn(__fadd_rn(x1, __fmul_rn(0.5f, w)), __fmul_rn(dx, w));
    float nh = __fmul_rn(h, expf(dh));
    float nw = __fmul_rn(w, expf(dw));
    float oy1 = __fsub_rn(cy, __fmul_rn(0.5f, nh));
    float ox1 = __fsub_rn(cx, __fmul_rn(0.5f, nw));
    float oy2 = __fadd_rn(cy, __fmul_rn(0.5f, nh));
    float ox2 = __fadd_rn(cx, __fmul_rn(0.5f, nw));
    oy1 = fminf(fmaxf(oy1, wy1), wy2);
    ox1 = fminf(fmaxf(ox1, wx1), wx2);
    oy2 = fminf(fmaxf(oy2, wy1), wy2);
    ox2 = fminf(fmaxf(ox2, wx1), wx2);
    return make_float4(oy1, ox1, oy2, ox2);
}

// Block-wide exclusive scan over per-thread pair counts (1024 threads = 32 warps).
__device__ __forceinline__ int scan_pairs(int cnt, int tid, int* s_warp, int* total) {
    int lane = tid & 31, warp = tid >> 5;
    int inc = cnt;
#pragma unroll
    for (int d = 1; d < 32; d <<= 1) {
        int v = __shfl_up_sync(0xffffffffu, inc, d);
        if (lane >= d) inc += v;
    }
    if (lane == 31) s_warp[warp] = inc;
    __syncthreads();
    if (warp == 0) {
        int v = s_warp[lane];
#pragma unroll
        for (int d = 1; d < 32; d <<= 1) {
            int u = __shfl_up_sync(0xffffffffu, v, d);
            if (lane >= d) v += u;
        }
        s_warp[lane] = v;
    }
    __syncthreads();
    *total = s_warp[31];
    int we = (warp == 0) ? 0 : s_warp[warp - 1];
    return we + inc - cnt;
}

extern "C" __global__ void __launch_bounds__(NTHREADS, 1)
detection_kernel(const float* __restrict__ rois,
                 const float* __restrict__ probs,
                 const float* __restrict__ bbox,
                 const float* __restrict__ meta,
                 float* __restrict__ out) {
    extern __shared__ unsigned char dsm[];
    u64* s_keys = (u64*)(dsm + OFF_KEYS);
    float4* s_obox = (float4*)(dsm + OFF_OBOX);
    float4* s_sbox = (float4*)(dsm + OFF_SBOX);
    unsigned short* s_sidx = (unsigned short*)(dsm + OFF_SIDX);
    unsigned char* s_cls = (unsigned char*)(dsm + OFF_CLS);
    unsigned short* s_compact = (unsigned short*)(dsm + OFF_COMPACT);
    unsigned char* s_ccls = (unsigned char*)(dsm + OFF_CCLS);
    unsigned char* s_elig = (unsigned char*)(dsm + OFF_ELIG);
    unsigned short* s_out = (unsigned short*)(dsm + OFF_OUT);
    int* s_warp = (int*)(dsm + OFF_WARP);
    int* s_stats = (int*)(dsm + OFF_STATS);
    u64* s_remv = (u64*)(dsm + OFF_REMV);
    u64* s_mask = (u64*)(dsm + OFF_MASK);

    const int tid = threadIdx.x;
    const int b = blockIdx.x;

    // window per batch (scale uses image_meta row 0, window uses row b)
    float ih = meta[4];
    float iw = meta[5];
    float sy = __fsub_rn(ih, 1.0f);
    float sx = __fsub_rn(iw, 1.0f);
    const float* mb = meta + (size_t)b * METAS;
    float wy1 = __fsub_rn(mb[7], 0.0f) / sy;
    float wx1 = __fsub_rn(mb[8], 0.0f) / sx;
    float wy2 = __fsub_rn(mb[9], 1.0f) / sy;
    float wx2 = __fsub_rn(mb[10], 1.0f) / sx;

    if (tid == 0) s_stats[0] = 0;
    __syncthreads();

    // ---------- Phase A: per-ROI argmax, refine, offset box; emit valid keys ----------
    for (int n = tid; n < NN; n += NTHREADS) {
        int base = b * NN + n;
        const float* pr = probs + (size_t)base * CC;
        float best = pr[0];
        int cls = 0;
#pragma unroll 4
        for (int c = 1; c < CC; c++) {
            float p = pr[c];
            if (p > best) { best = p; cls = c; }
        }
        float score = best;
        bool valid = (cls > 0) && (score >= 0.7f);
        float4 rb = refine_box(rois, bbox, base, cls, wy1, wx1, wy2, wx2);
        float off = __fmul_rn(4.0f, (float)cls);
        float4 ob;
        ob.x = __fadd_rn(rb.x, off);
        ob.y = __fadd_rn(rb.y, off);
        ob.z = __fadd_rn(rb.z, off);
        ob.w = __fadd_rn(rb.w, off);
        s_obox[n] = ob;
        s_cls[n] = (unsigned char)cls;
        if (valid) {
            unsigned int sb = __float_as_uint(score);   // positive float: bits monotonic
            u64 key = ((u64)sb << 11) | (u64)(2047 - n); // score desc, idx asc
            int pos = atomicAdd(&s_stats[0], 1);
            s_keys[pos] = key;
        }
    }
    __syncthreads();
    const int V = s_stats[0];

    if (V > 0) {
        // P = next pow2 >= max(V,2)
        int P = 2;
        while (P < V) P <<= 1;

        // pad keys
        for (int n = V + tid; n < P; n += NTHREADS) s_keys[n] = 0ull;
        __syncthreads();

        // ---------- Phase B: bitonic sort descending (P elements, P/2 <= 1024 pairs) ----------
        const int half = P >> 1;
        for (int k = 2; k <= P; k <<= 1) {
            for (int j = k >> 1; j > 0; j >>= 1) {
                if (tid < half) {
                    int i = ((tid & ~(j - 1)) << 1) | (tid & (j - 1));
                    int p = i | j;
                    bool up = ((i & k) == 0);
                    u64 ki = s_keys[i], kp = s_keys[p];
                    bool doswap = up ? (ki < kp) : (ki > kp);
                    if (doswap) { s_keys[i] = kp; s_keys[p] = ki; }
                }
                __syncthreads();
            }
        }

        // ---------- Phase B2: sorted index + sorted boxes ----------
        for (int i = tid; i < V; i += NTHREADS) {
            u64 key = s_keys[i];
            int orig = 2047 - (int)(key & 2047ull);
            s_sidx[i] = (unsigned short)orig;
            s_sbox[i] = s_obox[orig];
        }
        __syncthreads();

        // ---------- Phase C: suppression bit-matrix ----------
        const int W = (V + 63) >> 6;
        const bool fast = (V <= MAXV_SMEM);
        u64* maskp = fast ? s_mask : (g_mask + (size_t)b * NPAD * WMAX);
        const int totalW = V * W;
        for (int idx = tid; idx < totalW; idx += NTHREADS) {
            int i = idx / W;
            int w = idx - i * W;
            u64 bits = 0ull;
            if (w >= (i >> 6)) {
                float4 bi = s_sbox[i];
                float ai = __fmul_rn(__fsub_rn(bi.z, bi.x), __fsub_rn(bi.w, bi.y));
                int j0 = w << 6;
                int jn = V - j0; if (jn > 64) jn = 64;
                for (int t = 0; t < jn; t++) {
                    int j = j0 + t;
                    if (j > i) {
                        float4 bj = s_sbox[j];
                        float iy = fmaxf(0.0f, __fsub_rn(fminf(bi.z, bj.z), fmaxf(bi.x, bj.x)));
                        float ix = fmaxf(0.0f, __fsub_rn(fminf(bi.w, bj.w), fmaxf(bi.y, bj.y)));
                        float inter = __fmul_rn(iy, ix);
                        float aj = __fmul_rn(__fsub_rn(bj.z, bj.x), __fsub_rn(bj.w, bj.y));
                        float den = __fadd_rn(__fsub_rn(__fadd_rn(ai, aj), inter), 1e-12f);
                        float iou = inter / den;
                        if (iou > 0.3f) bits |= (1ull << t);
                    }
                }
            }
            maskp[(size_t)i * W + w] = bits;
        }
        __syncthreads();

        // ---------- Phase D: warp-serial greedy sweep ----------
        if (tid < 32) {
            u64 remv = 0ull;
            int curw = 0;
            u64 curbits = 0ull;
            for (int i = 0; i < V; i++) {
                int w = i >> 6;
                if (w != curw) {
                    curw = w;
                    curbits = __shfl_sync(0xffffffffu, remv, w);
                }
                if (!((curbits >> (i & 63)) & 1ull)) {
                    u64 m = (tid < W) ? maskp[(size_t)i * W + tid] : 0ull;
                    remv |= m;
                    curbits = __shfl_sync(0xffffffffu, remv, curw);
                }
            }
            s_remv[tid] = remv;
        }
        __syncthreads();
    }

    // ---------- Phase E: compact kept entries in sorted order ----------
    int p0 = 2 * tid, p1 = 2 * tid + 1;
    int e0 = (p0 < V) && !((s_remv[p0 >> 6] >> (p0 & 63)) & 1ull);
    int e1 = (p1 < V) && !((s_remv[p1 >> 6] >> (p1 & 63)) & 1ull);
    if (V == 0) { e0 = 0; e1 = 0; }
    int m_total;
    int pos = scan_pairs(e0 + e1, tid, s_warp, &m_total);
    if (e0) { s_compact[pos] = (unsigned short)p0; s_ccls[pos] = s_cls[s_sidx[p0]]; }
    if (e1) { s_compact[pos + e0] = (unsigned short)p1; s_ccls[pos + e0] = s_cls[s_sidx[p1]]; }
    __syncthreads();
    const int m = m_total;

    // ---------- Phase F: per-class rank cap (rank < MAXI) ----------
    for (int k = tid; k < NPAD; k += NTHREADS) {
        if (k < m) {
            unsigned char ck = s_ccls[k];
            int r = 0;
            for (int l = 0; l < k; l++) r += (s_ccls[l] == ck) ? 1 : 0;
            s_elig[k] = (r < MAXI) ? 1 : 0;
        } else {
            s_elig[k] = 0;
        }
    }
    __syncthreads();

    // ---------- Phase G: first 100 eligible in sorted order (== top_k) ----------
    int g0 = s_elig[2 * tid];
    int g1 = s_elig[2 * tid + 1];
    int elig_total;
    int opos = scan_pairs(g0 + g1, tid, s_warp, &elig_total);
    if (g0 && opos < MAXI) s_out[opos] = s_compact[2 * tid];
    if (g1 && (opos + g0) < MAXI) s_out[opos + g0] = s_compact[2 * tid + 1];
    __syncthreads();
    const int outCount = (elig_total < MAXI) ? elig_total : MAXI;

    // ---------- Phase H: write output ----------
    for (int r = tid; r < MAXI; r += NTHREADS) {
        float v0 = 0.f, v1 = 0.f, v2 = 0.f, v3 = 0.f, v4 = 0.f, v5 = 0.f;
        if (r < outCount) {
            int p = s_out[r];
            int orig = s_sidx[p];
            int cls = s_cls[orig];
            float sc = __uint_as_float((unsigned int)(s_keys[p] >> 11));
            float4 rb = refine_box(rois, bbox, b * NN + orig, cls, wy1, wx1, wy2, wx2);
            v0 = rb.x; v1 = rb.y; v2 = rb.z; v3 = rb.w;
            v4 = (float)cls; v5 = sc;
        }
        float* o = out + ((size_t)b * MAXI + r) * 6;
        o[0] = v0; o[1] = v1; o[2] = v2; o[3] = v3; o[4] = v4; o[5] = v5;
    }
}

extern "C" void kernel_launch(void* const* d_in, const int* in_sizes, int n_in,
                              void* d_out, int out_size) {
    const float* rois  = (const float*)d_in[0];
    const float* probs = (const float*)d_in[1];
    const float* bbox  = (const float*)d_in[2];
    const float* meta  = (const float*)d_in[3];
    float* out = (float*)d_out;

    cudaFuncSetAttribute(detection_kernel,
                         cudaFuncAttributeMaxDynamicSharedMemorySize, SMEM_BYTES);
    detection_kernel<<<BB, NTHREADS, SMEM_BYTES>>>(rois, probs, bbox, meta, out);
}

// round 3
// speedup vs baseline: 1.5154x; 1.5154x over previous
#include <cuda_runtime.h>
#include <math.h>

#define BB 8
#define NN 2000
#define CC 81
#define NPAD 2048
#define METAS 93
#define MAXI 100
#define NTHREADS 1024
#define MAXV_SMEM 1024
#define WMAX 32

typedef unsigned long long u64;

// -------- per-ROI scratch written by kernel1, read by kernel2 --------
__device__ float4 g_obox[BB * NN];   // class-offset box (for NMS)
__device__ float4 g_rbox[BB * NN];   // refined+clipped box (for output)
__device__ float  g_score[BB * NN];  // score, or -1 if invalid
__device__ int    g_cls[BB * NN];

// fallback mask scratch for V > 1024 (rarely taken)
__device__ u64 g_mask[(size_t)BB * NPAD * WMAX];

// -------- kernel2 dynamic smem layout (bytes) --------
#define OFF_KEYS    0        // u64[2048]      16384
#define OFF_OBOX    16384    // float4[2048]   32768 -> 49152
#define OFF_SBOX    49152    // float4[2048]   32768 -> 81920
#define OFF_SIDX    81920    // ushort[2048]    4096 -> 86016
#define OFF_CLS     86016    // uchar[2048]     2048 -> 88064
#define OFF_COMPACT 88064    // ushort[2048]    4096 -> 92160
#define OFF_CCLS    92160    // uchar[2048]     2048 -> 94208
#define OFF_ELIG    94208    // uchar[2048]     2048 -> 96256
#define OFF_OUT     96256    // ushort[128]      256 -> 96512
#define OFF_WARP    96512    // int[32]          128 -> 96640
#define OFF_STATS   96640    // int[8]            32 -> 96672
#define OFF_REMV    96672    // u64[32]          256 -> 96928
#define OFF_MASK    96928    // u64[1024*16]  131072 -> 228000
#define SMEM_BYTES  228000

// ================= Kernel 1: one warp per ROI, full chip =================
__global__ void __launch_bounds__(256)
prep_kernel(const float* __restrict__ rois,
            const float* __restrict__ probs,
            const float* __restrict__ bbox,
            const float* __restrict__ meta) {
    const int lane = threadIdx.x & 31;
    const int warp = threadIdx.x >> 5;
    const int roi = blockIdx.x * 8 + warp;   // 8 warps/block
    if (roi >= BB * NN) return;
    const int b = roi / NN;

    // ---- warp-cooperative argmax over 81 classes (first-max tie-break) ----
    const float* pr = probs + (size_t)roi * CC;
    float best = -1.0f;
    int bidx = CC;
#pragma unroll
    for (int k = 0; k < 3; k++) {
        int c = lane + 32 * k;
        if (c < CC) {
            float p = pr[c];
            if (p > best) { best = p; bidx = c; }  // per-lane indices increase: strict > = first max
        }
    }
#pragma unroll
    for (int d = 16; d > 0; d >>= 1) {
        float ob = __shfl_xor_sync(0xffffffffu, best, d);
        int oi = __shfl_xor_sync(0xffffffffu, bidx, d);
        if (ob > best || (ob == best && oi < bidx)) { best = ob; bidx = oi; }
    }

    if (lane == 0) {
        const int cls = bidx;
        const float score = best;

        // window for this image
        float ih = meta[4];
        float iw = meta[5];
        float sy = __fsub_rn(ih, 1.0f);
        float sx = __fsub_rn(iw, 1.0f);
        const float* mb = meta + (size_t)b * METAS;
        float wy1 = __fsub_rn(mb[7], 0.0f) / sy;
        float wx1 = __fsub_rn(mb[8], 0.0f) / sx;
        float wy2 = __fsub_rn(mb[9], 1.0f) / sy;
        float wx2 = __fsub_rn(mb[10], 1.0f) / sx;

        // refine + clip (exact reference ops, no FMA contraction)
        float4 rv = ((const float4*)rois)[roi];
        float4 dv = ((const float4*)bbox)[(size_t)roi * CC + cls];
        float dy = __fmul_rn(dv.x, 0.1f);
        float dx = __fmul_rn(dv.y, 0.1f);
        float dh = __fmul_rn(dv.z, 0.2f);
        float dw = __fmul_rn(dv.w, 0.2f);
        float h = __fsub_rn(rv.z, rv.x);
        float w = __fsub_rn(rv.w, rv.y);
        float cy = __fadd_rn(__fadd_rn(rv.x, __fmul_rn(0.5f, h)), __fmul_rn(dy, h));
        float cx = __fadd_rn(__fadd_rn(rv.y, __fmul_rn(0.5f, w)), __fmul_rn(dx, w));
        float nh = __fmul_rn(h, expf(dh));
        float nw = __fmul_rn(w, expf(dw));
        float oy1 = fminf(fmaxf(__fsub_rn(cy, __fmul_rn(0.5f, nh)), wy1), wy2);
        float ox1 = fminf(fmaxf(__fsub_rn(cx, __fmul_rn(0.5f, nw)), wx1), wx2);
        float oy2 = fminf(fmaxf(__fadd_rn(cy, __fmul_rn(0.5f, nh)), wy1), wy2);
        float ox2 = fminf(fmaxf(__fadd_rn(cx, __fmul_rn(0.5f, nw)), wx1), wx2);

        float off = __fmul_rn(4.0f, (float)cls);
        g_rbox[roi] = make_float4(oy1, ox1, oy2, ox2);
        g_obox[roi] = make_float4(__fadd_rn(oy1, off), __fadd_rn(ox1, off),
                                  __fadd_rn(oy2, off), __fadd_rn(ox2, off));
        g_cls[roi] = cls;
        bool valid = (cls > 0) && (score >= 0.7f);
        g_score[roi] = valid ? score : -1.0f;
    }
}

// Block-wide exclusive scan over per-thread pair counts (1024 threads = 32 warps).
__device__ __forceinline__ int scan_pairs(int cnt, int tid, int* s_warp, int* total) {
    int lane = tid & 31, warp = tid >> 5;
    int inc = cnt;
#pragma unroll
    for (int d = 1; d < 32; d <<= 1) {
        int v = __shfl_up_sync(0xffffffffu, inc, d);
        if (lane >= d) inc += v;
    }
    if (lane == 31) s_warp[warp] = inc;
    __syncthreads();
    if (warp == 0) {
        int v = s_warp[lane];
#pragma unroll
        for (int d = 1; d < 32; d <<= 1) {
            int u = __shfl_up_sync(0xffffffffu, v, d);
            if (lane >= d) v += u;
        }
        s_warp[lane] = v;
    }
    __syncthreads();
    *total = s_warp[31];
    int we = (warp == 0) ? 0 : s_warp[warp - 1];
    return we + inc - cnt;
}

// ================= Kernel 2: per-image sort + NMS + select =================
__global__ void __launch_bounds__(NTHREADS, 1)
select_kernel(float* __restrict__ out) {
    extern __shared__ unsigned char dsm[];
    u64* s_keys = (u64*)(dsm + OFF_KEYS);
    float4* s_obox = (float4*)(dsm + OFF_OBOX);
    float4* s_sbox = (float4*)(dsm + OFF_SBOX);
    unsigned short* s_sidx = (unsigned short*)(dsm + OFF_SIDX);
    unsigned char* s_cls = (unsigned char*)(dsm + OFF_CLS);
    unsigned short* s_compact = (unsigned short*)(dsm + OFF_COMPACT);
    unsigned char* s_ccls = (unsigned char*)(dsm + OFF_CCLS);
    unsigned char* s_elig = (unsigned char*)(dsm + OFF_ELIG);
    unsigned short* s_out = (unsigned short*)(dsm + OFF_OUT);
    int* s_warp = (int*)(dsm + OFF_WARP);
    int* s_stats = (int*)(dsm + OFF_STATS);
    u64* s_remv = (u64*)(dsm + OFF_REMV);
    u64* s_mask = (u64*)(dsm + OFF_MASK);

    const int tid = threadIdx.x;
    const int b = blockIdx.x;

    if (tid == 0) s_stats[0] = 0;
    __syncthreads();

    // ---------- Phase A': load per-ROI records (coalesced), build keys ----------
    for (int n = tid; n < NN; n += NTHREADS) {
        int base = b * NN + n;
        s_obox[n] = g_obox[base];
        s_cls[n] = (unsigned char)g_cls[base];
        float score = g_score[base];
        if (score > 0.0f) {
            unsigned int sb = __float_as_uint(score);
            u64 key = ((u64)sb << 11) | (u64)(2047 - n);  // score desc, idx asc
            int pos = atomicAdd(&s_stats[0], 1);
            s_keys[pos] = key;
        }
    }
    __syncthreads();
    const int V = s_stats[0];

    if (V > 0) {
        int P = 2;
        while (P < V) P <<= 1;
        for (int n = V + tid; n < P; n += NTHREADS) s_keys[n] = 0ull;
        __syncthreads();

        // ---------- Phase B: bitonic sort descending ----------
        const int half = P >> 1;
        for (int k = 2; k <= P; k <<= 1) {
            for (int j = k >> 1; j > 0; j >>= 1) {
                if (tid < half) {
                    int i = ((tid & ~(j - 1)) << 1) | (tid & (j - 1));
                    int p = i | j;
                    bool up = ((i & k) == 0);
                    u64 ki = s_keys[i], kp = s_keys[p];
                    bool doswap = up ? (ki < kp) : (ki > kp);
                    if (doswap) { s_keys[i] = kp; s_keys[p] = ki; }
                }
                __syncthreads();
            }
        }

        // ---------- Phase B2: sorted index + sorted boxes ----------
        for (int i = tid; i < V; i += NTHREADS) {
            u64 key = s_keys[i];
            int orig = 2047 - (int)(key & 2047ull);
            s_sidx[i] = (unsigned short)orig;
            s_sbox[i] = s_obox[orig];
        }
        __syncthreads();

        // ---------- Phase C: suppression bit-matrix ----------
        const int W = (V + 63) >> 6;
        const bool fast = (V <= MAXV_SMEM);
        u64* maskp = fast ? s_mask : (g_mask + (size_t)b * NPAD * WMAX);
        const int totalW = V * W;
        for (int idx = tid; idx < totalW; idx += NTHREADS) {
            int i = idx / W;
            int w = idx - i * W;
            u64 bits = 0ull;
            if (w >= (i >> 6)) {
                float4 bi = s_sbox[i];
                float ai = __fmul_rn(__fsub_rn(bi.z, bi.x), __fsub_rn(bi.w, bi.y));
                int j0 = w << 6;
                int jn = V - j0; if (jn > 64) jn = 64;
                for (int t = 0; t < jn; t++) {
                    int j = j0 + t;
                    if (j > i) {
                        float4 bj = s_sbox[j];
                        float iy = fmaxf(0.0f, __fsub_rn(fminf(bi.z, bj.z), fmaxf(bi.x, bj.x)));
                        float ix = fmaxf(0.0f, __fsub_rn(fminf(bi.w, bj.w), fmaxf(bi.y, bj.y)));
                        float inter = __fmul_rn(iy, ix);
                        float aj = __fmul_rn(__fsub_rn(bj.z, bj.x), __fsub_rn(bj.w, bj.y));
                        float den = __fadd_rn(__fsub_rn(__fadd_rn(ai, aj), inter), 1e-12f);
                        float iou = inter / den;
                        if (iou > 0.3f) bits |= (1ull << t);
                    }
                }
            }
            maskp[(size_t)i * W + w] = bits;
        }
        __syncthreads();

        // ---------- Phase D: warp-serial greedy sweep ----------
        if (tid < 32) {
            u64 remv = 0ull;
            int curw = 0;
            u64 curbits = 0ull;
            for (int i = 0; i < V; i++) {
                int w = i >> 6;
                if (w != curw) {
                    curw = w;
                    curbits = __shfl_sync(0xffffffffu, remv, w);
                }
                if (!((curbits >> (i & 63)) & 1ull)) {
                    u64 m = (tid < W) ? maskp[(size_t)i * W + tid] : 0ull;
                    remv |= m;
                    curbits = __shfl_sync(0xffffffffu, remv, curw);
                }
            }
            s_remv[tid] = remv;
        }
        __syncthreads();
    }

    // ---------- Phase E: compact kept entries in sorted order ----------
    int p0 = 2 * tid, p1 = 2 * tid + 1;
    int e0 = (p0 < V) && !((s_remv[p0 >> 6] >> (p0 & 63)) & 1ull);
    int e1 = (p1 < V) && !((s_remv[p1 >> 6] >> (p1 & 63)) & 1ull);
    if (V == 0) { e0 = 0; e1 = 0; }
    int m_total;
    int pos = scan_pairs(e0 + e1, tid, s_warp, &m_total);
    if (e0) { s_compact[pos] = (unsigned short)p0; s_ccls[pos] = s_cls[s_sidx[p0]]; }
    if (e1) { s_compact[pos + e0] = (unsigned short)p1; s_ccls[pos + e0] = s_cls[s_sidx[p1]]; }
    __syncthreads();
    const int m = m_total;

    // ---------- Phase F: per-class rank cap (rank < MAXI) ----------
    for (int k = tid; k < NPAD; k += NTHREADS) {
        if (k < m) {
            unsigned char ck = s_ccls[k];
            int r = 0;
            for (int l = 0; l < k; l++) r += (s_ccls[l] == ck) ? 1 : 0;
            s_elig[k] = (r < MAXI) ? 1 : 0;
        } else {
            s_elig[k] = 0;
        }
    }
    __syncthreads();

    // ---------- Phase G: first 100 eligible in sorted order ----------
    int g0 = s_elig[2 * tid];
    int g1 = s_elig[2 * tid + 1];
    int elig_total;
    int opos = scan_pairs(g0 + g1, tid, s_warp, &elig_total);
    if (g0 && opos < MAXI) s_out[opos] = s_compact[2 * tid];
    if (g1 && (opos + g0) < MAXI) s_out[opos + g0] = s_compact[2 * tid + 1];
    __syncthreads();
    const int outCount = (elig_total < MAXI) ? elig_total : MAXI;

    // ---------- Phase H: write output ----------
    for (int r = tid; r < MAXI; r += NTHREADS) {
        float v0 = 0.f, v1 = 0.f, v2 = 0.f, v3 = 0.f, v4 = 0.f, v5 = 0.f;
        if (r < outCount) {
            int p = s_out[r];
            int orig = s_sidx[p];
            float4 rb = g_rbox[b * NN + orig];
            v0 = rb.x; v1 = rb.y; v2 = rb.z; v3 = rb.w;
            v4 = (float)s_cls[orig];
            v5 = __uint_as_float((unsigned int)(s_keys[p] >> 11));
        }
        float* o = out + ((size_t)b * MAXI + r) * 6;
        o[0] = v0; o[1] = v1; o[2] = v2; o[3] = v3; o[4] = v4; o[5] = v5;
    }
}

extern "C" void kernel_launch(void* const* d_in, const int* in_sizes, int n_in,
                              void* d_out, int out_size) {
    const float* rois  = (const float*)d_in[0];
    const float* probs = (const float*)d_in[1];
    const float* bbox  = (const float*)d_in[2];
    const float* meta  = (const float*)d_in[3];
    float* out = (float*)d_out;

    cudaFuncSetAttribute(select_kernel,
                         cudaFuncAttributeMaxDynamicSharedMemorySize, SMEM_BYTES);

    prep_kernel<<<(BB * NN + 7) / 8, 256>>>(rois, probs, bbox, meta);
    select_kernel<<<BB, NTHREADS, SMEM_BYTES>>>(out);
}

// round 4
// speedup vs baseline: 9.6382x; 6.3602x over previous
#include <cuda_runtime.h>
#include <math.h>

#define BB 8
#define NN 2000
#define CC 81
#define NPAD 2048
#define METAS 93
#define MAXI 100
#define NTHREADS 1024

typedef unsigned long long u64;

// -------- per-ROI scratch written by kernel1, read by kernel2 --------
__device__ float4 g_obox[BB * NN];   // class-offset box (for NMS)
__device__ float4 g_rbox[BB * NN];   // refined+clipped box (for output)
__device__ float  g_score[BB * NN];  // score, or -1 if invalid
__device__ int    g_cls[BB * NN];

// -------- kernel2 dynamic smem layout (bytes) --------
#define OFF_KEYS    0        // u64[2048]        16384
#define OFF_OBOX    16384    // float4[2048]     32768 -> 49152
#define OFF_SBOX    49152    // float4[2048]     32768 -> 81920
#define OFF_SIDX    81920    // ushort[2048]      4096 -> 86016
#define OFF_SCLS    86016    // uchar[2048]       2048 -> 88064
#define OFF_CLS     88064    // uchar[2048]       2048 -> 90112
#define OFF_KEEP    90112    // uchar[2048]       2048 -> 92160
#define OFF_ELIG    92160    // uchar[2048]       2048 -> 94208
#define OFF_OUT     94208    // ushort[128]        256 -> 94464
#define OFF_WARP    94464    // int[32]            128 -> 94592
#define OFF_STATS   94592    // int[8]              32 -> 94624
#define OFF_WBUF    94624    // ushort[32*2048] 131072 -> 225696
#define SMEM_BYTES  225696

// ================= Kernel 1: one warp per ROI, full chip =================
__global__ void __launch_bounds__(256)
prep_kernel(const float* __restrict__ rois,
            const float* __restrict__ probs,
            const float* __restrict__ bbox,
            const float* __restrict__ meta) {
    const int lane = threadIdx.x & 31;
    const int warp = threadIdx.x >> 5;
    const int roi = blockIdx.x * 8 + warp;   // 8 warps/block
    if (roi >= BB * NN) return;
    const int b = roi / NN;

    // ---- warp-cooperative argmax over 81 classes (first-max tie-break) ----
    const float* pr = probs + (size_t)roi * CC;
    float best = -1.0f;
    int bidx = CC;
#pragma unroll
    for (int k = 0; k < 3; k++) {
        int c = lane + 32 * k;
        if (c < CC) {
            float p = pr[c];
            if (p > best) { best = p; bidx = c; }  // per-lane idx increases: strict > = first max
        }
    }
#pragma unroll
    for (int d = 16; d > 0; d >>= 1) {
        float ob = __shfl_xor_sync(0xffffffffu, best, d);
        int oi = __shfl_xor_sync(0xffffffffu, bidx, d);
        if (ob > best || (ob == best && oi < bidx)) { best = ob; bidx = oi; }
    }

    if (lane == 0) {
        const int cls = bidx;
        const float score = best;

        float ih = meta[4];
        float iw = meta[5];
        float sy = __fsub_rn(ih, 1.0f);
        float sx = __fsub_rn(iw, 1.0f);
        const float* mb = meta + (size_t)b * METAS;
        float wy1 = __fsub_rn(mb[7], 0.0f) / sy;
        float wx1 = __fsub_rn(mb[8], 0.0f) / sx;
        float wy2 = __fsub_rn(mb[9], 1.0f) / sy;
        float wx2 = __fsub_rn(mb[10], 1.0f) / sx;

        // refine + clip (exact reference ops, no FMA contraction)
        float4 rv = ((const float4*)rois)[roi];
        float4 dv = ((const float4*)bbox)[(size_t)roi * CC + cls];
        float dy = __fmul_rn(dv.x, 0.1f);
        float dx = __fmul_rn(dv.y, 0.1f);
        float dh = __fmul_rn(dv.z, 0.2f);
        float dw = __fmul_rn(dv.w, 0.2f);
        float h = __fsub_rn(rv.z, rv.x);
        float w = __fsub_rn(rv.w, rv.y);
        float cy = __fadd_rn(__fadd_rn(rv.x, __fmul_rn(0.5f, h)), __fmul_rn(dy, h));
        float cx = __fadd_rn(__fadd_rn(rv.y, __fmul_rn(0.5f, w)), __fmul_rn(dx, w));
        float nh = __fmul_rn(h, expf(dh));
        float nw = __fmul_rn(w, expf(dw));
        float oy1 = fminf(fmaxf(__fsub_rn(cy, __fmul_rn(0.5f, nh)), wy1), wy2);
        float ox1 = fminf(fmaxf(__fsub_rn(cx, __fmul_rn(0.5f, nw)), wx1), wx2);
        float oy2 = fminf(fmaxf(__fadd_rn(cy, __fmul_rn(0.5f, nh)), wy1), wy2);
        float ox2 = fminf(fmaxf(__fadd_rn(cx, __fmul_rn(0.5f, nw)), wx1), wx2);

        float off = __fmul_rn(4.0f, (float)cls);
        g_rbox[roi] = make_float4(oy1, ox1, oy2, ox2);
        g_obox[roi] = make_float4(__fadd_rn(oy1, off), __fadd_rn(ox1, off),
                                  __fadd_rn(oy2, off), __fadd_rn(ox2, off));
        g_cls[roi] = cls;
        bool valid = (cls > 0) && (score >= 0.7f);
        g_score[roi] = valid ? score : -1.0f;
    }
}

// Block-wide exclusive scan over per-thread pair counts (1024 threads = 32 warps).
__device__ __forceinline__ int scan_pairs(int cnt, int tid, int* s_warp, int* total) {
    int lane = tid & 31, warp = tid >> 5;
    int inc = cnt;
#pragma unroll
    for (int d = 1; d < 32; d <<= 1) {
        int v = __shfl_up_sync(0xffffffffu, inc, d);
        if (lane >= d) inc += v;
    }
    if (lane == 31) s_warp[warp] = inc;
    __syncthreads();
    if (warp == 0) {
        int v = s_warp[lane];
#pragma unroll
        for (int d = 1; d < 32; d <<= 1) {
            int u = __shfl_up_sync(0xffffffffu, v, d);
            if (lane >= d) v += u;
        }
        s_warp[lane] = v;
    }
    __syncthreads();
    *total = s_warp[31];
    int we = (warp == 0) ? 0 : s_warp[warp - 1];
    return we + inc - cnt;
}

// ================= Kernel 2: per-image sort + per-class NMS + select =================
__global__ void __launch_bounds__(NTHREADS, 1)
select_kernel(float* __restrict__ out) {
    extern __shared__ unsigned char dsm[];
    u64* s_keys = (u64*)(dsm + OFF_KEYS);
    float4* s_obox = (float4*)(dsm + OFF_OBOX);
    float4* s_sbox = (float4*)(dsm + OFF_SBOX);
    unsigned short* s_sidx = (unsigned short*)(dsm + OFF_SIDX);
    unsigned char* s_scls = (unsigned char*)(dsm + OFF_SCLS);
    unsigned char* s_cls = (unsigned char*)(dsm + OFF_CLS);
    unsigned char* s_keep = (unsigned char*)(dsm + OFF_KEEP);
    unsigned char* s_elig = (unsigned char*)(dsm + OFF_ELIG);
    unsigned short* s_out = (unsigned short*)(dsm + OFF_OUT);
    int* s_warp = (int*)(dsm + OFF_WARP);
    int* s_stats = (int*)(dsm + OFF_STATS);

    const int tid = threadIdx.x;
    const int lane = tid & 31;
    const int warp = tid >> 5;
    const int b = blockIdx.x;

    if (tid == 0) s_stats[0] = 0;
    __syncthreads();

    // ---------- Phase A': load per-ROI records (coalesced), build keys ----------
    for (int n = tid; n < NN; n += NTHREADS) {
        int base = b * NN + n;
        s_obox[n] = g_obox[base];
        s_cls[n] = (unsigned char)g_cls[base];
        float score = g_score[base];
        if (score > 0.0f) {
            unsigned int sb = __float_as_uint(score);
            u64 key = ((u64)sb << 11) | (u64)(2047 - n);  // score desc, idx asc
            int pos = atomicAdd(&s_stats[0], 1);
            s_keys[pos] = key;
        }
    }
    // init flags
    for (int n = tid; n < NPAD; n += NTHREADS) { s_keep[n] = 1; s_elig[n] = 0; }
    __syncthreads();
    const int V = s_stats[0];

    if (V > 0) {
        int P = 2;
        while (P < V) P <<= 1;
        for (int n = V + tid; n < P; n += NTHREADS) s_keys[n] = 0ull;
        __syncthreads();

        // ---------- Phase B: bitonic sort descending ----------
        const int half = P >> 1;
        for (int k = 2; k <= P; k <<= 1) {
            for (int j = k >> 1; j > 0; j >>= 1) {
                if (tid < half) {
                    int i = ((tid & ~(j - 1)) << 1) | (tid & (j - 1));
                    int p = i | j;
                    bool up = ((i & k) == 0);
                    u64 ki = s_keys[i], kp = s_keys[p];
                    bool doswap = up ? (ki < kp) : (ki > kp);
                    if (doswap) { s_keys[i] = kp; s_keys[p] = ki; }
                }
                __syncthreads();
            }
        }

        // ---------- Phase B2: sorted index, class, boxes ----------
        for (int i = tid; i < V; i += NTHREADS) {
            u64 key = s_keys[i];
            int orig = 2047 - (int)(key & 2047ull);
            s_sidx[i] = (unsigned short)orig;
            unsigned char c = s_cls[orig];
            s_scls[i] = c;
            s_sbox[i] = s_obox[orig];
        }
        __syncthreads();

        // ---------- Phase D': per-class NMS, one warp per class ----------
        // Cross-class IoU is exactly 0 (class offset 4*cls on boxes in [0,1]),
        // so the greedy NMS decomposes into independent per-class NMS.
        unsigned short* wbuf = (unsigned short*)(dsm + OFF_WBUF) + warp * NPAD;
        volatile unsigned char* vkeep = (volatile unsigned char*)s_keep;
        for (int c = (warp == 0) ? 32 : warp; c < CC; c += 32) {
            // gather this class's sorted positions (ordered)
            int L = 0;
            for (int base = 0; base < V; base += 32) {
                int i = base + lane;
                bool is = (i < V) && (s_scls[i] == (unsigned char)c);
                unsigned int m = __ballot_sync(0xffffffffu, is);
                int pre = __popc(m & ((1u << lane) - 1u));
                if (is) wbuf[L + pre] = (unsigned short)i;
                L += __popc(m);
            }
            // greedy NMS within class, fold in per-class MAXI cap
            int keptc = 0;
            for (int a = 0; a < L; a++) {
                int pi = wbuf[a];
                if (vkeep[pi]) {
                    float4 bi = s_sbox[pi];
                    float ai = __fmul_rn(__fsub_rn(bi.z, bi.x), __fsub_rn(bi.w, bi.y));
                    for (int bp = a + 1 + lane; bp < L; bp += 32) {
                        int pj = wbuf[bp];
                        if (vkeep[pj]) {
                            float4 bj = s_sbox[pj];
                            float iy = fmaxf(0.0f, __fsub_rn(fminf(bi.z, bj.z), fmaxf(bi.x, bj.x)));
                            float ix = fmaxf(0.0f, __fsub_rn(fminf(bi.w, bj.w), fmaxf(bi.y, bj.y)));
                            float inter = __fmul_rn(iy, ix);
                            float aj = __fmul_rn(__fsub_rn(bj.z, bj.x), __fsub_rn(bj.w, bj.y));
                            float den = __fadd_rn(__fsub_rn(__fadd_rn(ai, aj), inter), 1e-12f);
                            if (inter / den > 0.3f) vkeep[pj] = 0;
                        }
                    }
                    if (lane == 0 && keptc < MAXI) s_elig[pi] = 1;
                    keptc++;
                }
                __syncwarp();
            }
        }
        __syncthreads();
    }

    // ---------- Phase G: first 100 eligible in sorted order (== top_k) ----------
    int p0 = 2 * tid, p1 = 2 * tid + 1;
    int g0 = s_elig[p0];
    int g1 = s_elig[p1];
    int elig_total;
    int opos = scan_pairs(g0 + g1, tid, s_warp, &elig_total);
    if (g0 && opos < MAXI) s_out[opos] = (unsigned short)p0;
    if (g1 && (opos + g0) < MAXI) s_out[opos + g0] = (unsigned short)p1;
    __syncthreads();
    const int outCount = (elig_total < MAXI) ? elig_total : MAXI;

    // ---------- Phase H: write output ----------
    for (int r = tid; r < MAXI; r += NTHREADS) {
        float v0 = 0.f, v1 = 0.f, v2 = 0.f, v3 = 0.f, v4 = 0.f, v5 = 0.f;
        if (r < outCount) {
            int p = s_out[r];
            int orig = s_sidx[p];
            float4 rb = g_rbox[b * NN + orig];
            v0 = rb.x; v1 = rb.y; v2 = rb.z; v3 = rb.w;
            v4 = (float)s_scls[p];
            v5 = __uint_as_float((unsigned int)(s_keys[p] >> 11));
        }
        float* o = out + ((size_t)b * MAXI + r) * 6;
        o[0] = v0; o[1] = v1; o[2] = v2; o[3] = v3; o[4] = v4; o[5] = v5;
    }
}

extern "C" void kernel_launch(void* const* d_in, const int* in_sizes, int n_in,
                              void* d_out, int out_size) {
    const float* rois  = (const float*)d_in[0];
    const float* probs = (const float*)d_in[1];
    const float* bbox  = (const float*)d_in[2];
    const float* meta  = (const float*)d_in[3];
    float* out = (float*)d_out;

    cudaFuncSetAttribute(select_kernel,
                         cudaFuncAttributeMaxDynamicSharedMemorySize, SMEM_BYTES);

    prep_kernel<<<(BB * NN + 7) / 8, 256>>>(rois, probs, bbox, meta);
    select_kernel<<<BB, NTHREADS, SMEM_BYTES>>>(out);
}